// round 9
// baseline (speedup 1.0000x reference)
#include <cuda_runtime.h>
#include <cuda_bf16.h>
#include <cstdint>

// FSQ: q = round(4*tanh( W @ LayerNorm(x) )), folded into a single pass:
//   logit_n = rstd * (dot(x, gamma*W_n) - mu * s_n) + b_n
// R9: R=3 rows/warp, SCALAR dot accumulators (24 regs; f32x2 banks proved to
// strangle the scheduler in R5/R8), f32x2 stats, full LDG.128 double-buffer.
// ~80 regs -> __launch_bounds__(256,3) -> 24 warps/SM. All accesses 128-bit.

typedef unsigned long long u64;

__device__ __forceinline__ void fma2(u64 &d, u64 a, u64 b) {
    asm("fma.rn.f32x2 %0, %1, %2, %0;" : "+l"(d) : "l"(a), "l"(b));
}
__device__ __forceinline__ void add2(u64 &d, u64 a) {
    asm("add.rn.f32x2 %0, %0, %1;" : "+l"(d) : "l"(a));
}
__device__ __forceinline__ u64 pack2(float a, float b) {
    u64 r;
    asm("mov.b64 %0, {%1, %2};" : "=l"(r) : "r"(__float_as_uint(a)), "r"(__float_as_uint(b)));
    return r;
}
__device__ __forceinline__ float2 up2(u64 v) {
    unsigned a, b;
    asm("mov.b64 {%0, %1}, %2;" : "=r"(a), "=r"(b) : "l"(v));
    return make_float2(__uint_as_float(a), __uint_as_float(b));
}
__device__ __forceinline__ float pairsum(u64 v) {
    float2 f = up2(v);
    return f.x + f.y;
}

// rintf(4*tanh(x)), fast-math-proof (fmaf/rcp.rn/sqrt.rn only).
__device__ __forceinline__ float tanh4_round(float x) {
    float ax = fabsf(x);
    float r;
    if (ax >= 1.5f) {
        r = 4.0f;   // 4*tanh(1.5)=3.6206 -> 4; monotone beyond
    } else {
        const float T2L = 2.8853900817779268f;   // 2*log2(e)
        float t = ax * T2L;
        float k = rintf(t);
        float f = t - k;
        float y = f * 0.6931471805599453f;
        float p = 1.9841269841e-4f;
        p = fmaf(p, y, 1.3888888888e-3f);
        p = fmaf(p, y, 8.3333333333e-3f);
        p = fmaf(p, y, 4.1666666667e-2f);
        p = fmaf(p, y, 1.6666666667e-1f);
        p = fmaf(p, y, 0.5f);
        p = fmaf(p, y, 1.0f);
        p = fmaf(p, y, 1.0f);
        float scale = __int_as_float(((int)k + 127) << 23);
        float e = p * scale;                     // exp(2*ax)
        float th = (e - 1.0f) * __frcp_rn(e + 1.0f);
        r = rintf(4.0f * th);
    }
    return copysignf(r, x);
}

static const int D       = 1024;
static const int F4      = 256;   // 16B chunks per row
static const int NL      = 8;
static const int WPAD    = 9;     // float4 entries per chunk (8 + 1 pad)
static const int R       = 3;     // rows per warp
static const int ROWS_PB = 24;    // 8 warps * 3 rows

__global__ void __launch_bounds__(256, 3)
fsq_kernel(const float* __restrict__ x, const float* __restrict__ gamma,
           const float* __restrict__ beta, const float* __restrict__ W,
           float* __restrict__ out, int rows)
{
    __shared__ float4 sW[F4 * WPAD];       // 36864 B: W'[chunk][level]
    __shared__ float sStats[ROWS_PB][12];  // per-slot: sum, sumsq, 8 dots
    __shared__ float sRed[8][16];
    __shared__ float sSB[16];              // s[0..7], b[0..7]

    const int tid  = threadIdx.x;
    const int lane = tid & 31;
    const int wid  = tid >> 5;

    // ---------------- prep: W' = gamma*W into smem; s_n, b_n ----------------
    float sP[NL], bP[NL];
#pragma unroll
    for (int n = 0; n < NL; n++) { sP[n] = 0.0f; bP[n] = 0.0f; }
    {
        const float4* g4 = (const float4*)gamma;  // [256]
        const float4* e4 = (const float4*)beta;
        const float4* W4 = (const float4*)W;      // [8][256]
        int i = tid;                              // 256 threads = 256 chunks
        float4 g = g4[i];
        float4 b = e4[i];
#pragma unroll
        for (int n = 0; n < NL; n++) {
            float4 w = W4[n * F4 + i];
            float4 p;
            p.x = g.x * w.x; p.y = g.y * w.y; p.z = g.z * w.z; p.w = g.w * w.w;
            sW[i * WPAD + n] = p;
            sP[n] += (p.x + p.y) + (p.z + p.w);
            bP[n] += (b.x * w.x + b.y * w.y) + (b.z * w.z + b.w * w.w);
        }
    }
#pragma unroll
    for (int o = 16; o; o >>= 1) {
#pragma unroll
        for (int n = 0; n < NL; n++) {
            sP[n] += __shfl_xor_sync(0xffffffffu, sP[n], o);
            bP[n] += __shfl_xor_sync(0xffffffffu, bP[n], o);
        }
    }
    if (lane == 0) {
#pragma unroll
        for (int n = 0; n < NL; n++) {
            sRed[wid][n]     = sP[n];
            sRed[wid][8 + n] = bP[n];
        }
    }
    __syncthreads();
    if (tid < 16) {
        float v = 0.0f;
#pragma unroll
        for (int w = 0; w < 8; w++) v += sRed[w][tid];
        sSB[tid] = v;
    }
    __syncthreads();

    // ---------------- main: 3 rows per warp, single pass ----------------
    int rowBase = blockIdx.x * ROWS_PB + wid * R;
    if (rowBase > rows - R) rowBase = rows - R;   // clamp (overlap idempotent)
    if (rowBase < 0) rowBase = 0;
    const float4* bp = (const float4*)x + (size_t)rowBase * F4 + lane;

    float dots[R][NL];                 // scalar accumulators (24 regs)
    u64 sum2[R], ssq2[R];              // f32x2 stats (12 regs)
#pragma unroll
    for (int r = 0; r < R; r++) {
        sum2[r] = 0ull; ssq2[r] = 0ull;
#pragma unroll
        for (int n = 0; n < NL; n++) dots[r][n] = 0.0f;
    }

    float4 c[R];
#pragma unroll
    for (int r = 0; r < R; r++) c[r] = __ldcs(bp + r * F4);

#pragma unroll
    for (int s = 0; s < 8; s++) {
        float4 nx[R];
        if (s < 7) {
#pragma unroll
            for (int r = 0; r < R; r++)
                nx[r] = __ldcs(bp + r * F4 + (s + 1) * 32);
        }
        // stats (f32x2)
#pragma unroll
        for (int r = 0; r < R; r++) {
            u64 a = pack2(c[r].x, c[r].y);
            u64 b = pack2(c[r].z, c[r].w);
            add2(sum2[r], a); add2(sum2[r], b);
            fma2(ssq2[r], a, a); fma2(ssq2[r], b, b);
        }
        // dots (scalar, W entry read once, serves 3 rows)
        const float4* wrow = &sW[(s * 32 + lane) * WPAD];
#pragma unroll
        for (int n = 0; n < NL; n++) {
            float4 w = wrow[n];
#pragma unroll
            for (int r = 0; r < R; r++) {
                float d = dots[r][n];
                d = fmaf(c[r].x, w.x, d);
                d = fmaf(c[r].y, w.y, d);
                d = fmaf(c[r].z, w.z, d);
                d = fmaf(c[r].w, w.w, d);
                dots[r][n] = d;
            }
        }
#pragma unroll
        for (int r = 0; r < R; r++) c[r] = nx[r];
    }

    // ---------------- reduce + stash stats ----------------
#pragma unroll
    for (int r = 0; r < R; r++) {
        float s = pairsum(sum2[r]);
        float q = pairsum(ssq2[r]);
        float dv[NL];
#pragma unroll
        for (int n = 0; n < NL; n++) dv[n] = dots[r][n];
#pragma unroll
        for (int o = 16; o; o >>= 1) {
            s += __shfl_xor_sync(0xffffffffu, s, o);
            q += __shfl_xor_sync(0xffffffffu, q, o);
#pragma unroll
            for (int n = 0; n < NL; n++)
                dv[n] += __shfl_xor_sync(0xffffffffu, dv[n], o);
        }
        if (lane == 0) {
            sStats[wid * R + r][0] = s;
            sStats[wid * R + r][1] = q;
#pragma unroll
            for (int n = 0; n < NL; n++) sStats[wid * R + r][2 + n] = dv[n];
        }
    }
    __syncthreads();

    // ---------------- tail: 192 threads = 24 slots x 8 levels ----------------
    if (tid < ROWS_PB * NL) {
        int rr = tid >> 3;                 // slot 0..23
        int n  = tid & 7;
        // recompute the same clamped row this slot's warp used
        int rb = blockIdx.x * ROWS_PB + (rr / R) * R;
        if (rb > rows - R) rb = rows - R;
        if (rb < 0) rb = 0;
        int orow = rb + (rr % R);
        float s  = sStats[rr][0];
        float q  = sStats[rr][1];
        float dv = sStats[rr][2 + n];
        float mu   = s * (1.0f / 1024.0f);
        float var  = fmaf(-mu, mu, q * (1.0f / 1024.0f));
        float rstd = __frcp_rn(__fsqrt_rn(var + 1e-5f));
        float lg   = fmaf(rstd, fmaf(-mu, sSB[n], dv), sSB[8 + n]);
        out[(size_t)orow * NL + n] = tanh4_round(lg);
    }
}

extern "C" void kernel_launch(void* const* d_in, const int* in_sizes, int n_in,
                              void* d_out, int out_size)
{
    const float* x     = (const float*)d_in[0];  // [8,8192,1024]
    const float* gamma = (const float*)d_in[1];  // [1024]
    const float* beta  = (const float*)d_in[2];  // [1024]
    const float* W     = (const float*)d_in[3];  // [8,1024]
    float* out = (float*)d_out;                  // [8,8192,8]

    int rows = in_sizes[0] / D;
    int grid = (rows + ROWS_PB - 1) / ROWS_PB;
    fsq_kernel<<<grid, 256>>>(x, gamma, beta, W, out, rows);
}

// round 10
// speedup vs baseline: 1.0310x; 1.0310x over previous
#include <cuda_runtime.h>
#include <cuda_bf16.h>
#include <cstdint>

// FSQ: q = round(4*tanh( W @ LayerNorm(x) )), folded into a single pass:
//   logit_n = rstd * (dot(x, gamma*W_n) - mu * s_n) + b_n
// R10: R=4 rows/warp (minimum l1tex wavefronts/row: 3.0) at 3 blocks/SM
// (24 warps). All-scalar accumulators (dots 32 + stats 8 regs), no manual
// double-buffer: fully-unrolled loop + reg headroom lets ptxas hoist __ldcs
// loads itself. All accesses 128-bit. W' float4 smem, stride 9 (conflict-free).

typedef unsigned long long u64;

__device__ __forceinline__ float2 up2(u64 v) {
    unsigned a, b;
    asm("mov.b64 {%0, %1}, %2;" : "=r"(a), "=r"(b) : "l"(v));
    return make_float2(__uint_as_float(a), __uint_as_float(b));
}

// rintf(4*tanh(x)), fast-math-proof (fmaf/rcp.rn/sqrt.rn only).
__device__ __forceinline__ float tanh4_round(float x) {
    float ax = fabsf(x);
    float r;
    if (ax >= 1.5f) {
        r = 4.0f;   // 4*tanh(1.5)=3.6206 -> 4; monotone beyond
    } else {
        const float T2L = 2.8853900817779268f;   // 2*log2(e)
        float t = ax * T2L;
        float k = rintf(t);
        float f = t - k;
        float y = f * 0.6931471805599453f;
        float p = 1.9841269841e-4f;
        p = fmaf(p, y, 1.3888888888e-3f);
        p = fmaf(p, y, 8.3333333333e-3f);
        p = fmaf(p, y, 4.1666666667e-2f);
        p = fmaf(p, y, 1.6666666667e-1f);
        p = fmaf(p, y, 0.5f);
        p = fmaf(p, y, 1.0f);
        p = fmaf(p, y, 1.0f);
        float scale = __int_as_float(((int)k + 127) << 23);
        float e = p * scale;                     // exp(2*ax)
        float th = (e - 1.0f) * __frcp_rn(e + 1.0f);
        r = rintf(4.0f * th);
    }
    return copysignf(r, x);
}

static const int D       = 1024;
static const int F4      = 256;   // 16B chunks per row
static const int NL      = 8;
static const int WPAD    = 9;     // float4 entries per chunk (8 + 1 pad)
static const int R       = 4;     // rows per warp
static const int ROWS_PB = 32;    // 8 warps * 4 rows

__global__ void __launch_bounds__(256, 3)
fsq_kernel(const float* __restrict__ x, const float* __restrict__ gamma,
           const float* __restrict__ beta, const float* __restrict__ W,
           float* __restrict__ out, int rows)
{
    __shared__ float4 sW[F4 * WPAD];       // 36864 B: W'[chunk][level]
    __shared__ float sStats[ROWS_PB][12];  // per-slot: sum, sumsq, 8 dots
    __shared__ float sRed[8][16];
    __shared__ float sSB[16];              // s[0..7], b[0..7]

    const int tid  = threadIdx.x;
    const int lane = tid & 31;
    const int wid  = tid >> 5;

    // ---------------- prep: W' = gamma*W into smem; s_n, b_n ----------------
    float sP[NL], bP[NL];
#pragma unroll
    for (int n = 0; n < NL; n++) { sP[n] = 0.0f; bP[n] = 0.0f; }
    {
        const float4* g4 = (const float4*)gamma;  // [256]
        const float4* e4 = (const float4*)beta;
        const float4* W4 = (const float4*)W;      // [8][256]
        int i = tid;                              // 256 threads = 256 chunks
        float4 g = g4[i];
        float4 b = e4[i];
#pragma unroll
        for (int n = 0; n < NL; n++) {
            float4 w = W4[n * F4 + i];
            float4 p;
            p.x = g.x * w.x; p.y = g.y * w.y; p.z = g.z * w.z; p.w = g.w * w.w;
            sW[i * WPAD + n] = p;
            sP[n] += (p.x + p.y) + (p.z + p.w);
            bP[n] += (b.x * w.x + b.y * w.y) + (b.z * w.z + b.w * w.w);
        }
    }
#pragma unroll
    for (int o = 16; o; o >>= 1) {
#pragma unroll
        for (int n = 0; n < NL; n++) {
            sP[n] += __shfl_xor_sync(0xffffffffu, sP[n], o);
            bP[n] += __shfl_xor_sync(0xffffffffu, bP[n], o);
        }
    }
    if (lane == 0) {
#pragma unroll
        for (int n = 0; n < NL; n++) {
            sRed[wid][n]     = sP[n];
            sRed[wid][8 + n] = bP[n];
        }
    }
    __syncthreads();
    if (tid < 16) {
        float v = 0.0f;
#pragma unroll
        for (int w = 0; w < 8; w++) v += sRed[w][tid];
        sSB[tid] = v;
    }
    __syncthreads();

    // ---------------- main: 4 rows per warp, single pass ----------------
    int rowBase = blockIdx.x * ROWS_PB + wid * R;
    if (rowBase > rows - R) rowBase = rows - R;   // clamp (overlap idempotent)
    if (rowBase < 0) rowBase = 0;
    const float4* bp = (const float4*)x + (size_t)rowBase * F4 + lane;

    float dots[R][NL];                 // scalar accumulators (32 regs)
    float sum[R], ssq[R];              // scalar stats (8 regs)
#pragma unroll
    for (int r = 0; r < R; r++) {
        sum[r] = 0.0f; ssq[r] = 0.0f;
#pragma unroll
        for (int n = 0; n < NL; n++) dots[r][n] = 0.0f;
    }

#pragma unroll
    for (int s = 0; s < 8; s++) {
        float4 c[R];
#pragma unroll
        for (int r = 0; r < R; r++)
            c[r] = __ldcs(bp + r * F4 + s * 32);

        // stats (scalar)
#pragma unroll
        for (int r = 0; r < R; r++) {
            sum[r] += (c[r].x + c[r].y) + (c[r].z + c[r].w);
            float q = ssq[r];
            q = fmaf(c[r].x, c[r].x, q);
            q = fmaf(c[r].y, c[r].y, q);
            q = fmaf(c[r].z, c[r].z, q);
            q = fmaf(c[r].w, c[r].w, q);
            ssq[r] = q;
        }
        // dots (scalar, W entry read once, serves 4 rows)
        const float4* wrow = &sW[(s * 32 + lane) * WPAD];
#pragma unroll
        for (int n = 0; n < NL; n++) {
            float4 w = wrow[n];
#pragma unroll
            for (int r = 0; r < R; r++) {
                float d = dots[r][n];
                d = fmaf(c[r].x, w.x, d);
                d = fmaf(c[r].y, w.y, d);
                d = fmaf(c[r].z, w.z, d);
                d = fmaf(c[r].w, w.w, d);
                dots[r][n] = d;
            }
        }
    }

    // ---------------- reduce + stash stats ----------------
#pragma unroll
    for (int r = 0; r < R; r++) {
        float s = sum[r];
        float q = ssq[r];
        float dv[NL];
#pragma unroll
        for (int n = 0; n < NL; n++) dv[n] = dots[r][n];
#pragma unroll
        for (int o = 16; o; o >>= 1) {
            s += __shfl_xor_sync(0xffffffffu, s, o);
            q += __shfl_xor_sync(0xffffffffu, q, o);
#pragma unroll
            for (int n = 0; n < NL; n++)
                dv[n] += __shfl_xor_sync(0xffffffffu, dv[n], o);
        }
        if (lane == 0) {
            sStats[wid * R + r][0] = s;
            sStats[wid * R + r][1] = q;
#pragma unroll
            for (int n = 0; n < NL; n++) sStats[wid * R + r][2 + n] = dv[n];
        }
    }
    __syncthreads();

    // ---------------- tail: 256 threads = 32 slots x 8 levels ----------------
    {
        int rr = tid >> 3;                 // slot 0..31
        int n  = tid & 7;
        // recompute the same clamped row this slot's warp used
        int rb = blockIdx.x * ROWS_PB + (rr / R) * R;
        if (rb > rows - R) rb = rows - R;
        if (rb < 0) rb = 0;
        int orow = rb + (rr % R);
        float s  = sStats[rr][0];
        float q  = sStats[rr][1];
        float dv = sStats[rr][2 + n];
        float mu   = s * (1.0f / 1024.0f);
        float var  = fmaf(-mu, mu, q * (1.0f / 1024.0f));
        float rstd = __frcp_rn(__fsqrt_rn(var + 1e-5f));
        float lg   = fmaf(rstd, fmaf(-mu, sSB[n], dv), sSB[8 + n]);
        out[(size_t)orow * NL + n] = tanh4_round(lg);
    }
}

extern "C" void kernel_launch(void* const* d_in, const int* in_sizes, int n_in,
                              void* d_out, int out_size)
{
    const float* x     = (const float*)d_in[0];  // [8,8192,1024]
    const float* gamma = (const float*)d_in[1];  // [1024]
    const float* beta  = (const float*)d_in[2];  // [1024]
    const float* W     = (const float*)d_in[3];  // [8,1024]
    float* out = (float*)d_out;                  // [8,8192,8]

    int rows = in_sizes[0] / D;
    int grid = (rows + ROWS_PB - 1) / ROWS_PB;
    fsq_kernel<<<grid, 256>>>(x, gamma, beta, W, out, rows);
}

// round 11
// speedup vs baseline: 1.0593x; 1.0274x over previous
#include <cuda_runtime.h>
#include <cuda_bf16.h>
#include <cstdint>

// FSQ: q = round(4*tanh( W @ LayerNorm(x) )), folded into a single pass:
//   logit_n = rstd * (dot(x, gamma*W_n) - mu * s_n) + b_n
// R11: 4-deep cp.async pipeline (3 stages of 16KB in flight), ONE barrier per
// stage. Consumer warps have zero LDG in stream: 8 LDS.128 + scalar FMAs per
// stage (R10 consume structure). 8 warps x 4 rows = 32 rows/block, 2 blocks/SM.

typedef unsigned long long u64;

// rintf(4*tanh(x)), fast-math-proof (fmaf/rcp.rn/sqrt.rn only).
__device__ __forceinline__ float tanh4_round(float x) {
    float ax = fabsf(x);
    float r;
    if (ax >= 1.5f) {
        r = 4.0f;   // 4*tanh(1.5)=3.6206 -> 4; monotone beyond
    } else {
        const float T2L = 2.8853900817779268f;   // 2*log2(e)
        float t = ax * T2L;
        float k = rintf(t);
        float f = t - k;
        float y = f * 0.6931471805599453f;
        float p = 1.9841269841e-4f;
        p = fmaf(p, y, 1.3888888888e-3f);
        p = fmaf(p, y, 8.3333333333e-3f);
        p = fmaf(p, y, 4.1666666667e-2f);
        p = fmaf(p, y, 1.6666666667e-1f);
        p = fmaf(p, y, 0.5f);
        p = fmaf(p, y, 1.0f);
        p = fmaf(p, y, 1.0f);
        float scale = __int_as_float(((int)k + 127) << 23);
        float e = p * scale;                     // exp(2*ax)
        float th = (e - 1.0f) * __frcp_rn(e + 1.0f);
        r = rintf(4.0f * th);
    }
    return copysignf(r, x);
}

static const int D       = 1024;
static const int F4      = 256;   // 16B chunks per row
static const int NL      = 8;
static const int WPAD    = 9;     // float4 entries per chunk (8 + 1 pad)
static const int R       = 4;     // rows per warp
static const int ROWS_PB = 32;    // 8 warps * 4 rows
static const int NSTAGE  = 8;     // stages of 32 chunks (512B/row)
static const int NBUF    = 4;     // pipeline depth (3 in flight)

// dynamic smem layout (bytes)
static const int SW_BYTES = F4 * WPAD * 16;             // 36864
static const int SX_BYTES = NBUF * ROWS_PB * 32 * 16;   // 65536
static const int ST_BYTES = ROWS_PB * 12 * 4;           // 1536
static const int SR_BYTES = 8 * 16 * 4;                 // 512
static const int SMEM_TOTAL = SW_BYTES + SX_BYTES + ST_BYTES + SR_BYTES + 64;

__global__ void __launch_bounds__(256, 2)
fsq_kernel(const float* __restrict__ x, const float* __restrict__ gamma,
           const float* __restrict__ beta, const float* __restrict__ W,
           float* __restrict__ out, int rows)
{
    extern __shared__ unsigned char smem_raw[];
    float4* sW = (float4*)smem_raw;                                // [F4*WPAD]
    float4* sX = (float4*)(smem_raw + SW_BYTES);                   // [NBUF][32][32]
    float (*sStats)[12] = (float(*)[12])(smem_raw + SW_BYTES + SX_BYTES);
    float (*sRed)[16]   = (float(*)[16])(smem_raw + SW_BYTES + SX_BYTES + ST_BYTES);
    float* sSB          = (float*)(smem_raw + SW_BYTES + SX_BYTES + ST_BYTES + SR_BYTES);

    const int tid  = threadIdx.x;
    const int lane = tid & 31;
    const int wid  = tid >> 5;

    int rowBase = blockIdx.x * ROWS_PB;
    if (rowBase > rows - ROWS_PB) rowBase = rows - ROWS_PB;  // safety
    if (rowBase < 0) rowBase = 0;

    const uint32_t sx_u32 = (uint32_t)__cvta_generic_to_shared(sX);
    const float4* x4 = (const float4*)x;

    // ---- cp.async stage issuer: stage s -> buffer (s & 3) ----
    // each thread copies 4x16B: rows wid, wid+8, wid+16, wid+24, chunk=lane
    auto issue_stage = [&](int s) {
        uint32_t dbase = sx_u32 + (uint32_t)(s & (NBUF - 1)) * (ROWS_PB * 32 * 16);
#pragma unroll
        for (int j = 0; j < 4; j++) {
            int row = wid + j * 8;
            const float4* src = x4 + (size_t)(rowBase + row) * F4 + s * 32 + lane;
            uint32_t dst = dbase + (uint32_t)(row * 32 + lane) * 16;
            asm volatile("cp.async.cg.shared.global [%0], [%1], 16;"
                         :: "r"(dst), "l"(src) : "memory");
        }
        asm volatile("cp.async.commit_group;" ::: "memory");
    };

    // prologue: 3 stages in flight before anything else
    issue_stage(0);
    issue_stage(1);
    issue_stage(2);

    // ---------------- prep: W' = gamma*W into smem; s_n, b_n ----------------
    float sP[NL], bP[NL];
#pragma unroll
    for (int n = 0; n < NL; n++) { sP[n] = 0.0f; bP[n] = 0.0f; }
    {
        const float4* g4 = (const float4*)gamma;  // [256]
        const float4* e4 = (const float4*)beta;
        const float4* W4 = (const float4*)W;      // [8][256]
        int i = tid;                              // 256 threads = 256 chunks
        float4 g = g4[i];
        float4 b = e4[i];
#pragma unroll
        for (int n = 0; n < NL; n++) {
            float4 w = W4[n * F4 + i];
            float4 p;
            p.x = g.x * w.x; p.y = g.y * w.y; p.z = g.z * w.z; p.w = g.w * w.w;
            sW[i * WPAD + n] = p;
            sP[n] += (p.x + p.y) + (p.z + p.w);
            bP[n] += (b.x * w.x + b.y * w.y) + (b.z * w.z + b.w * w.w);
        }
    }
#pragma unroll
    for (int o = 16; o; o >>= 1) {
#pragma unroll
        for (int n = 0; n < NL; n++) {
            sP[n] += __shfl_xor_sync(0xffffffffu, sP[n], o);
            bP[n] += __shfl_xor_sync(0xffffffffu, bP[n], o);
        }
    }
    if (lane == 0) {
#pragma unroll
        for (int n = 0; n < NL; n++) {
            sRed[wid][n]     = sP[n];
            sRed[wid][8 + n] = bP[n];
        }
    }
    __syncthreads();
    if (tid < 16) {
        float v = 0.0f;
#pragma unroll
        for (int w = 0; w < 8; w++) v += sRed[w][tid];
        sSB[tid] = v;
    }

    // ---------------- main: staged pipeline, one barrier per stage ----------
    float dots[R][NL];
    float sum[R], ssq[R];
#pragma unroll
    for (int r = 0; r < R; r++) {
        sum[r] = 0.0f; ssq[r] = 0.0f;
#pragma unroll
        for (int n = 0; n < NL; n++) dots[r][n] = 0.0f;
    }

#pragma unroll
    for (int s = 0; s < NSTAGE; s++) {
        // stage s landed (committed groups: 3+s; allow 2 pending -> 0..s done)
        asm volatile("cp.async.wait_group 2;" ::: "memory");
        // all warps done reading stage s-1's buffer; also orders sW on s==0
        __syncthreads();
        // refill the buffer freed by stage s-1 (buffer (s+3)&3)
        if (s + 3 < NSTAGE) {
            issue_stage(s + 3);
        } else {
            asm volatile("cp.async.commit_group;" ::: "memory");  // uniform count
        }

        // consume stage s: rows wid*4 .. wid*4+3, chunk = lane
        const float4* xbuf = sX + (s & (NBUF - 1)) * (ROWS_PB * 32)
                                + (wid * R) * 32 + lane;
        float4 c[R];
#pragma unroll
        for (int r = 0; r < R; r++) c[r] = xbuf[r * 32];

#pragma unroll
        for (int r = 0; r < R; r++) {
            sum[r] += (c[r].x + c[r].y) + (c[r].z + c[r].w);
            float q = ssq[r];
            q = fmaf(c[r].x, c[r].x, q);
            q = fmaf(c[r].y, c[r].y, q);
            q = fmaf(c[r].z, c[r].z, q);
            q = fmaf(c[r].w, c[r].w, q);
            ssq[r] = q;
        }
        const float4* wrow = &sW[(s * 32 + lane) * WPAD];
#pragma unroll
        for (int n = 0; n < NL; n++) {
            float4 w = wrow[n];
#pragma unroll
            for (int r = 0; r < R; r++) {
                float d = dots[r][n];
                d = fmaf(c[r].x, w.x, d);
                d = fmaf(c[r].y, w.y, d);
                d = fmaf(c[r].z, w.z, d);
                d = fmaf(c[r].w, w.w, d);
                dots[r][n] = d;
            }
        }
    }

    // ---------------- reduce + stash stats ----------------
#pragma unroll
    for (int r = 0; r < R; r++) {
        float s = sum[r];
        float q = ssq[r];
        float dv[NL];
#pragma unroll
        for (int n = 0; n < NL; n++) dv[n] = dots[r][n];
#pragma unroll
        for (int o = 16; o; o >>= 1) {
            s += __shfl_xor_sync(0xffffffffu, s, o);
            q += __shfl_xor_sync(0xffffffffu, q, o);
#pragma unroll
            for (int n = 0; n < NL; n++)
                dv[n] += __shfl_xor_sync(0xffffffffu, dv[n], o);
        }
        if (lane == 0) {
            sStats[wid * R + r][0] = s;
            sStats[wid * R + r][1] = q;
#pragma unroll
            for (int n = 0; n < NL; n++) sStats[wid * R + r][2 + n] = dv[n];
        }
    }
    __syncthreads();

    // ---------------- tail: 256 threads = 32 slots x 8 levels ----------------
    {
        int rr = tid >> 3;                 // slot 0..31
        int n  = tid & 7;
        int orow = rowBase + rr;
        float s  = sStats[rr][0];
        float q  = sStats[rr][1];
        float dv = sStats[rr][2 + n];
        float mu   = s * (1.0f / 1024.0f);
        float var  = fmaf(-mu, mu, q * (1.0f / 1024.0f));
        float rstd = __frcp_rn(__fsqrt_rn(var + 1e-5f));
        float lg   = fmaf(rstd, fmaf(-mu, sSB[n], dv), sSB[8 + n]);
        out[(size_t)orow * NL + n] = tanh4_round(lg);
    }
}

extern "C" void kernel_launch(void* const* d_in, const int* in_sizes, int n_in,
                              void* d_out, int out_size)
{
    const float* x     = (const float*)d_in[0];  // [8,8192,1024]
    const float* gamma = (const float*)d_in[1];  // [1024]
    const float* beta  = (const float*)d_in[2];  // [1024]
    const float* W     = (const float*)d_in[3];  // [8,1024]
    float* out = (float*)d_out;                  // [8,8192,8]

    static int smem_set = 0;
    if (!smem_set) {
        cudaFuncSetAttribute(fsq_kernel,
                             cudaFuncAttributeMaxDynamicSharedMemorySize,
                             SMEM_TOTAL);
        smem_set = 1;
    }

    int rows = in_sizes[0] / D;
    int grid = (rows + ROWS_PB - 1) / ROWS_PB;
    fsq_kernel<<<grid, 256, SMEM_TOTAL>>>(x, gamma, beta, W, out, rows);
}

// round 12
// speedup vs baseline: 1.0987x; 1.0372x over previous
#include <cuda_runtime.h>
#include <cuda_bf16.h>
#include <cstdint>

// FSQ: q = round(4*tanh( W @ LayerNorm(x) )), folded into a single pass:
//   logit_n = rstd * (dot(x, gamma*W_n) - mu * s_n) + b_n
// R12: R11's 4-deep cp.async pipeline (3 stages in flight, one barrier/stage)
// with f32x2 dot+stat accumulators. Consumers have zero LDG (c[] live ranges
// are short smem loads), so f32x2 fits: ~111 regs. Per warp-stage inst count
// drops ~150 -> ~100 (fma-pipe 140 -> 80).

typedef unsigned long long u64;

__device__ __forceinline__ void fma2(u64 &d, u64 a, u64 b) {
    asm("fma.rn.f32x2 %0, %1, %2, %0;" : "+l"(d) : "l"(a), "l"(b));
}
__device__ __forceinline__ void add2(u64 &d, u64 a) {
    asm("add.rn.f32x2 %0, %0, %1;" : "+l"(d) : "l"(a));
}
__device__ __forceinline__ float2 up2(u64 v) {
    unsigned a, b;
    asm("mov.b64 {%0, %1}, %2;" : "=r"(a), "=r"(b) : "l"(v));
    return make_float2(__uint_as_float(a), __uint_as_float(b));
}
__device__ __forceinline__ u64 pack2(float a, float b) {
    u64 r;
    asm("mov.b64 %0, {%1, %2};" : "=l"(r) : "r"(__float_as_uint(a)), "r"(__float_as_uint(b)));
    return r;
}
__device__ __forceinline__ float pairsum(u64 v) {
    float2 f = up2(v);
    return f.x + f.y;
}

// rintf(4*tanh(x)), fast-math-proof (fmaf/rcp.rn/sqrt.rn only).
__device__ __forceinline__ float tanh4_round(float x) {
    float ax = fabsf(x);
    float r;
    if (ax >= 1.5f) {
        r = 4.0f;   // 4*tanh(1.5)=3.6206 -> 4; monotone beyond
    } else {
        const float T2L = 2.8853900817779268f;   // 2*log2(e)
        float t = ax * T2L;
        float k = rintf(t);
        float f = t - k;
        float y = f * 0.6931471805599453f;
        float p = 1.9841269841e-4f;
        p = fmaf(p, y, 1.3888888888e-3f);
        p = fmaf(p, y, 8.3333333333e-3f);
        p = fmaf(p, y, 4.1666666667e-2f);
        p = fmaf(p, y, 1.6666666667e-1f);
        p = fmaf(p, y, 0.5f);
        p = fmaf(p, y, 1.0f);
        p = fmaf(p, y, 1.0f);
        float scale = __int_as_float(((int)k + 127) << 23);
        float e = p * scale;                     // exp(2*ax)
        float th = (e - 1.0f) * __frcp_rn(e + 1.0f);
        r = rintf(4.0f * th);
    }
    return copysignf(r, x);
}

static const int D       = 1024;
static const int F4      = 256;   // 16B chunks per row
static const int NL      = 8;
static const int WPAD    = 9;     // 16B entries per chunk (8 + 1 pad)
static const int R       = 4;     // rows per warp
static const int ROWS_PB = 32;    // 8 warps * 4 rows
static const int NSTAGE  = 8;     // stages of 32 chunks (512B/row)
static const int NBUF    = 4;     // pipeline depth (3 in flight)

// dynamic smem layout (bytes)
static const int SW_BYTES = F4 * WPAD * 16;             // 36864
static const int SX_BYTES = NBUF * ROWS_PB * 32 * 16;   // 65536
static const int ST_BYTES = ROWS_PB * 12 * 4;           // 1536
static const int SR_BYTES = 8 * 16 * 4;                 // 512
static const int SMEM_TOTAL = SW_BYTES + SX_BYTES + ST_BYTES + SR_BYTES + 64;

__global__ void __launch_bounds__(256, 2)
fsq_kernel(const float* __restrict__ x, const float* __restrict__ gamma,
           const float* __restrict__ beta, const float* __restrict__ W,
           float* __restrict__ out, int rows)
{
    extern __shared__ unsigned char smem_raw[];
    ulonglong2* sW = (ulonglong2*)smem_raw;                        // [F4*WPAD]
    ulonglong2* sX = (ulonglong2*)(smem_raw + SW_BYTES);           // [NBUF][32][32]
    float (*sStats)[12] = (float(*)[12])(smem_raw + SW_BYTES + SX_BYTES);
    float (*sRed)[16]   = (float(*)[16])(smem_raw + SW_BYTES + SX_BYTES + ST_BYTES);
    float* sSB          = (float*)(smem_raw + SW_BYTES + SX_BYTES + ST_BYTES + SR_BYTES);

    const int tid  = threadIdx.x;
    const int lane = tid & 31;
    const int wid  = tid >> 5;

    int rowBase = blockIdx.x * ROWS_PB;
    if (rowBase > rows - ROWS_PB) rowBase = rows - ROWS_PB;  // safety
    if (rowBase < 0) rowBase = 0;

    const uint32_t sx_u32 = (uint32_t)__cvta_generic_to_shared(sX);
    const float4* x4 = (const float4*)x;

    // ---- cp.async stage issuer: stage s -> buffer (s & 3) ----
    auto issue_stage = [&](int s) {
        uint32_t dbase = sx_u32 + (uint32_t)(s & (NBUF - 1)) * (ROWS_PB * 32 * 16);
#pragma unroll
        for (int j = 0; j < 4; j++) {
            int row = wid + j * 8;
            const float4* src = x4 + (size_t)(rowBase + row) * F4 + s * 32 + lane;
            uint32_t dst = dbase + (uint32_t)(row * 32 + lane) * 16;
            asm volatile("cp.async.cg.shared.global [%0], [%1], 16;"
                         :: "r"(dst), "l"(src) : "memory");
        }
        asm volatile("cp.async.commit_group;" ::: "memory");
    };

    // prologue: 3 stages in flight before anything else
    issue_stage(0);
    issue_stage(1);
    issue_stage(2);

    // ---------------- prep: W' = gamma*W into smem; s_n, b_n ----------------
    float sP[NL], bP[NL];
#pragma unroll
    for (int n = 0; n < NL; n++) { sP[n] = 0.0f; bP[n] = 0.0f; }
    {
        const float4* g4 = (const float4*)gamma;  // [256]
        const float4* e4 = (const float4*)beta;
        const float4* W4 = (const float4*)W;      // [8][256]
        int i = tid;                              // 256 threads = 256 chunks
        float4 g = g4[i];
        float4 b = e4[i];
#pragma unroll
        for (int n = 0; n < NL; n++) {
            float4 w = W4[n * F4 + i];
            float p0 = g.x * w.x, p1 = g.y * w.y, p2 = g.z * w.z, p3 = g.w * w.w;
            ulonglong2 e;
            e.x = pack2(p0, p1);
            e.y = pack2(p2, p3);
            sW[i * WPAD + n] = e;
            sP[n] += (p0 + p1) + (p2 + p3);
            bP[n] += (b.x * w.x + b.y * w.y) + (b.z * w.z + b.w * w.w);
        }
    }
#pragma unroll
    for (int o = 16; o; o >>= 1) {
#pragma unroll
        for (int n = 0; n < NL; n++) {
            sP[n] += __shfl_xor_sync(0xffffffffu, sP[n], o);
            bP[n] += __shfl_xor_sync(0xffffffffu, bP[n], o);
        }
    }
    if (lane == 0) {
#pragma unroll
        for (int n = 0; n < NL; n++) {
            sRed[wid][n]     = sP[n];
            sRed[wid][8 + n] = bP[n];
        }
    }
    __syncthreads();
    if (tid < 16) {
        float v = 0.0f;
#pragma unroll
        for (int w = 0; w < 8; w++) v += sRed[w][tid];
        sSB[tid] = v;
    }

    // ---------------- main: staged pipeline, one barrier per stage ----------
    u64 dots[R][NL];
    u64 sum2[R], ssq2[R];
#pragma unroll
    for (int r = 0; r < R; r++) {
        sum2[r] = 0ull; ssq2[r] = 0ull;
#pragma unroll
        for (int n = 0; n < NL; n++) dots[r][n] = 0ull;
    }

#pragma unroll
    for (int s = 0; s < NSTAGE; s++) {
        // stage s landed (committed: 3+s groups; 2 pending allowed)
        asm volatile("cp.async.wait_group 2;" ::: "memory");
        // all warps done reading stage s-1's buffer; also orders sW on s==0
        __syncthreads();
        // refill the buffer freed by stage s-1
        if (s + 3 < NSTAGE) {
            issue_stage(s + 3);
        } else {
            asm volatile("cp.async.commit_group;" ::: "memory");  // uniform count
        }

        // consume stage s: rows wid*4 .. wid*4+3, chunk = lane
        const ulonglong2* xbuf = sX + (s & (NBUF - 1)) * (ROWS_PB * 32)
                                    + (wid * R) * 32 + lane;
        ulonglong2 c[R];
#pragma unroll
        for (int r = 0; r < R; r++) c[r] = xbuf[r * 32];

        // stats (f32x2)
#pragma unroll
        for (int r = 0; r < R; r++) {
            add2(sum2[r], c[r].x); add2(sum2[r], c[r].y);
            fma2(ssq2[r], c[r].x, c[r].x);
            fma2(ssq2[r], c[r].y, c[r].y);
        }
        // dots (f32x2, W entry read once, serves 4 rows)
        const ulonglong2* wrow = &sW[(s * 32 + lane) * WPAD];
#pragma unroll
        for (int n = 0; n < NL; n++) {
            ulonglong2 w = wrow[n];
#pragma unroll
            for (int r = 0; r < R; r++) {
                fma2(dots[r][n], c[r].x, w.x);
                fma2(dots[r][n], c[r].y, w.y);
            }
        }
    }

    // ---------------- reduce + stash stats ----------------
#pragma unroll
    for (int r = 0; r < R; r++) {
        float s = pairsum(sum2[r]);
        float q = pairsum(ssq2[r]);
        float dv[NL];
#pragma unroll
        for (int n = 0; n < NL; n++) dv[n] = pairsum(dots[r][n]);
#pragma unroll
        for (int o = 16; o; o >>= 1) {
            s += __shfl_xor_sync(0xffffffffu, s, o);
            q += __shfl_xor_sync(0xffffffffu, q, o);
#pragma unroll
            for (int n = 0; n < NL; n++)
                dv[n] += __shfl_xor_sync(0xffffffffu, dv[n], o);
        }
        if (lane == 0) {
            sStats[wid * R + r][0] = s;
            sStats[wid * R + r][1] = q;
#pragma unroll
            for (int n = 0; n < NL; n++) sStats[wid * R + r][2 + n] = dv[n];
        }
    }
    __syncthreads();

    // ---------------- tail: 256 threads = 32 slots x 8 levels ----------------
    {
        int rr = tid >> 3;                 // slot 0..31
        int n  = tid & 7;
        int orow = rowBase + rr;
        float s  = sStats[rr][0];
        float q  = sStats[rr][1];
        float dv = sStats[rr][2 + n];
        float mu   = s * (1.0f / 1024.0f);
        float var  = fmaf(-mu, mu, q * (1.0f / 1024.0f));
        float rstd = __frcp_rn(__fsqrt_rn(var + 1e-5f));
        float lg   = fmaf(rstd, fmaf(-mu, sSB[n], dv), sSB[8 + n]);
        out[(size_t)orow * NL + n] = tanh4_round(lg);
    }
}

extern "C" void kernel_launch(void* const* d_in, const int* in_sizes, int n_in,
                              void* d_out, int out_size)
{
    const float* x     = (const float*)d_in[0];  // [8,8192,1024]
    const float* gamma = (const float*)d_in[1];  // [1024]
    const float* beta  = (const float*)d_in[2];  // [1024]
    const float* W     = (const float*)d_in[3];  // [8,1024]
    float* out = (float*)d_out;                  // [8,8192,8]

    static int smem_set = 0;
    if (!smem_set) {
        cudaFuncSetAttribute(fsq_kernel,
                             cudaFuncAttributeMaxDynamicSharedMemorySize,
                             SMEM_TOTAL);
        smem_set = 1;
    }

    int rows = in_sizes[0] / D;
    int grid = (rows + ROWS_PB - 1) / ROWS_PB;
    fsq_kernel<<<grid, 256, SMEM_TOTAL>>>(x, gamma, beta, W, out, rows);
}

// round 13
// speedup vs baseline: 1.0992x; 1.0005x over previous
#include <cuda_runtime.h>
#include <cuda_bf16.h>
#include <cstdint>

// FSQ: q = round(4*tanh( W @ LayerNorm(x) )), folded into a single pass:
//   logit_n = rstd * (dot(x, gamma*W_n) - mu * s_n) + b_n
// R13: WARP-PRIVATE 4-deep cp.async pipeline. Each warp copies its own 4 rows
// and syncs with wait_group + __syncwarp (cp.async state is per-thread) —
// zero block barriers in the mainloop (R12 paid 8). f32x2 dot+stat math.

typedef unsigned long long u64;

__device__ __forceinline__ void fma2(u64 &d, u64 a, u64 b) {
    asm("fma.rn.f32x2 %0, %1, %2, %0;" : "+l"(d) : "l"(a), "l"(b));
}
__device__ __forceinline__ void add2(u64 &d, u64 a) {
    asm("add.rn.f32x2 %0, %0, %1;" : "+l"(d) : "l"(a));
}
__device__ __forceinline__ float2 up2(u64 v) {
    unsigned a, b;
    asm("mov.b64 {%0, %1}, %2;" : "=r"(a), "=r"(b) : "l"(v));
    return make_float2(__uint_as_float(a), __uint_as_float(b));
}
__device__ __forceinline__ u64 pack2(float a, float b) {
    u64 r;
    asm("mov.b64 %0, {%1, %2};" : "=l"(r) : "r"(__float_as_uint(a)), "r"(__float_as_uint(b)));
    return r;
}
__device__ __forceinline__ float pairsum(u64 v) {
    float2 f = up2(v);
    return f.x + f.y;
}

// rintf(4*tanh(x)), fast-math-proof (fmaf/rcp.rn/sqrt.rn only).
__device__ __forceinline__ float tanh4_round(float x) {
    float ax = fabsf(x);
    float r;
    if (ax >= 1.5f) {
        r = 4.0f;   // 4*tanh(1.5)=3.6206 -> 4; monotone beyond
    } else {
        const float T2L = 2.8853900817779268f;   // 2*log2(e)
        float t = ax * T2L;
        float k = rintf(t);
        float f = t - k;
        float y = f * 0.6931471805599453f;
        float p = 1.9841269841e-4f;
        p = fmaf(p, y, 1.3888888888e-3f);
        p = fmaf(p, y, 8.3333333333e-3f);
        p = fmaf(p, y, 4.1666666667e-2f);
        p = fmaf(p, y, 1.6666666667e-1f);
        p = fmaf(p, y, 0.5f);
        p = fmaf(p, y, 1.0f);
        p = fmaf(p, y, 1.0f);
        float scale = __int_as_float(((int)k + 127) << 23);
        float e = p * scale;                     // exp(2*ax)
        float th = (e - 1.0f) * __frcp_rn(e + 1.0f);
        r = rintf(4.0f * th);
    }
    return copysignf(r, x);
}

static const int D       = 1024;
static const int F4      = 256;   // 16B chunks per row
static const int NL      = 8;
static const int WPAD    = 9;     // 16B entries per chunk (8 + 1 pad)
static const int R       = 4;     // rows per warp
static const int ROWS_PB = 32;    // 8 warps * 4 rows
static const int NSTAGE  = 8;     // stages of 32 chunks (512B/row)
static const int NBUF    = 4;     // pipeline depth (3 in flight)

// dynamic smem layout (bytes)
static const int SW_BYTES = F4 * WPAD * 16;             // 36864
static const int SX_BYTES = 8 * NBUF * R * 32 * 16;     // 65536 (8 warps)
static const int ST_BYTES = ROWS_PB * 12 * 4;           // 1536
static const int SR_BYTES = 8 * 16 * 4;                 // 512
static const int SMEM_TOTAL = SW_BYTES + SX_BYTES + ST_BYTES + SR_BYTES + 64;

__global__ void __launch_bounds__(256, 2)
fsq_kernel(const float* __restrict__ x, const float* __restrict__ gamma,
           const float* __restrict__ beta, const float* __restrict__ W,
           float* __restrict__ out, int rows)
{
    extern __shared__ unsigned char smem_raw[];
    ulonglong2* sW = (ulonglong2*)smem_raw;                        // [F4*WPAD]
    ulonglong2* sX = (ulonglong2*)(smem_raw + SW_BYTES);           // [8][NBUF][4][32]
    float (*sStats)[12] = (float(*)[12])(smem_raw + SW_BYTES + SX_BYTES);
    float (*sRed)[16]   = (float(*)[16])(smem_raw + SW_BYTES + SX_BYTES + ST_BYTES);
    float* sSB          = (float*)(smem_raw + SW_BYTES + SX_BYTES + ST_BYTES + SR_BYTES);

    const int tid  = threadIdx.x;
    const int lane = tid & 31;
    const int wid  = tid >> 5;

    int rowBase = blockIdx.x * ROWS_PB;
    if (rowBase > rows - ROWS_PB) rowBase = rows - ROWS_PB;  // safety
    if (rowBase < 0) rowBase = 0;

    // this warp's private smem region: NBUF stages x 4 rows x 32 chunks
    const uint32_t sx_u32 = (uint32_t)__cvta_generic_to_shared(sX)
                          + (uint32_t)wid * (NBUF * R * 32 * 16);
    const float4* x4 = (const float4*)x;
    const int myRow = rowBase + wid * R;

    // ---- warp-private cp.async stage issuer: stage s -> buffer (s & 3) ----
    // each lane copies chunk=lane of this warp's 4 rows
    auto issue_stage = [&](int s) {
        uint32_t dbase = sx_u32 + (uint32_t)(s & (NBUF - 1)) * (R * 32 * 16);
#pragma unroll
        for (int r = 0; r < R; r++) {
            const float4* src = x4 + (size_t)(myRow + r) * F4 + s * 32 + lane;
            uint32_t dst = dbase + (uint32_t)(r * 32 + lane) * 16;
            asm volatile("cp.async.cg.shared.global [%0], [%1], 16;"
                         :: "r"(dst), "l"(src) : "memory");
        }
        asm volatile("cp.async.commit_group;" ::: "memory");
    };

    // prologue: 3 stages in flight before anything else
    issue_stage(0);
    issue_stage(1);
    issue_stage(2);

    // ---------------- prep: W' = gamma*W into smem; s_n, b_n ----------------
    float sP[NL], bP[NL];
#pragma unroll
    for (int n = 0; n < NL; n++) { sP[n] = 0.0f; bP[n] = 0.0f; }
    {
        const float4* g4 = (const float4*)gamma;  // [256]
        const float4* e4 = (const float4*)beta;
        const float4* W4 = (const float4*)W;      // [8][256]
        int i = tid;                              // 256 threads = 256 chunks
        float4 g = g4[i];
        float4 b = e4[i];
#pragma unroll
        for (int n = 0; n < NL; n++) {
            float4 w = W4[n * F4 + i];
            float p0 = g.x * w.x, p1 = g.y * w.y, p2 = g.z * w.z, p3 = g.w * w.w;
            ulonglong2 e;
            e.x = pack2(p0, p1);
            e.y = pack2(p2, p3);
            sW[i * WPAD + n] = e;
            sP[n] += (p0 + p1) + (p2 + p3);
            bP[n] += (b.x * w.x + b.y * w.y) + (b.z * w.z + b.w * w.w);
        }
    }
#pragma unroll
    for (int o = 16; o; o >>= 1) {
#pragma unroll
        for (int n = 0; n < NL; n++) {
            sP[n] += __shfl_xor_sync(0xffffffffu, sP[n], o);
            bP[n] += __shfl_xor_sync(0xffffffffu, bP[n], o);
        }
    }
    if (lane == 0) {
#pragma unroll
        for (int n = 0; n < NL; n++) {
            sRed[wid][n]     = sP[n];
            sRed[wid][8 + n] = bP[n];
        }
    }
    __syncthreads();
    if (tid < 16) {
        float v = 0.0f;
#pragma unroll
        for (int w = 0; w < 8; w++) v += sRed[w][tid];
        sSB[tid] = v;
    }
    __syncthreads();   // sW (and sSB) visible to all warps; mainloop is barrier-free

    // ---------------- main: warp-private staged pipeline ----------------
    u64 dots[R][NL];
    u64 sum2[R], ssq2[R];
#pragma unroll
    for (int r = 0; r < R; r++) {
        sum2[r] = 0ull; ssq2[r] = 0ull;
#pragma unroll
        for (int n = 0; n < NL; n++) dots[r][n] = 0ull;
    }

#pragma unroll
    for (int s = 0; s < NSTAGE; s++) {
        // this warp's stage s landed (2 newer groups may still be pending)
        asm volatile("cp.async.wait_group 2;" ::: "memory");
        __syncwarp();   // lanes see each other's copied chunks

        // refill the buffer this warp freed at stage s-1
        if (s + 3 < NSTAGE) {
            issue_stage(s + 3);
        } else {
            asm volatile("cp.async.commit_group;" ::: "memory");  // uniform count
        }

        // consume stage s
        const ulonglong2* xbuf = (const ulonglong2*)
            (smem_raw + SW_BYTES) + (size_t)wid * (NBUF * R * 32)
            + (s & (NBUF - 1)) * (R * 32) + lane;
        ulonglong2 c[R];
#pragma unroll
        for (int r = 0; r < R; r++) c[r] = xbuf[r * 32];

        // stats (f32x2)
#pragma unroll
        for (int r = 0; r < R; r++) {
            add2(sum2[r], c[r].x); add2(sum2[r], c[r].y);
            fma2(ssq2[r], c[r].x, c[r].x);
            fma2(ssq2[r], c[r].y, c[r].y);
        }
        // dots (f32x2, W entry read once, serves 4 rows)
        const ulonglong2* wrow = &sW[(s * 32 + lane) * WPAD];
#pragma unroll
        for (int n = 0; n < NL; n++) {
            ulonglong2 w = wrow[n];
#pragma unroll
            for (int r = 0; r < R; r++) {
                fma2(dots[r][n], c[r].x, w.x);
                fma2(dots[r][n], c[r].y, w.y);
            }
        }
        __syncwarp();   // all lanes done reading buffer before it is refilled
    }

    // ---------------- reduce + stash stats ----------------
#pragma unroll
    for (int r = 0; r < R; r++) {
        float s = pairsum(sum2[r]);
        float q = pairsum(ssq2[r]);
        float dv[NL];
#pragma unroll
        for (int n = 0; n < NL; n++) dv[n] = pairsum(dots[r][n]);
#pragma unroll
        for (int o = 16; o; o >>= 1) {
            s += __shfl_xor_sync(0xffffffffu, s, o);
            q += __shfl_xor_sync(0xffffffffu, q, o);
#pragma unroll
            for (int n = 0; n < NL; n++)
                dv[n] += __shfl_xor_sync(0xffffffffu, dv[n], o);
        }
        if (lane == 0) {
            sStats[wid * R + r][0] = s;
            sStats[wid * R + r][1] = q;
#pragma unroll
            for (int n = 0; n < NL; n++) sStats[wid * R + r][2 + n] = dv[n];
        }
    }
    __syncthreads();

    // ---------------- tail: 256 threads = 32 slots x 8 levels ----------------
    {
        int rr = tid >> 3;                 // slot 0..31
        int n  = tid & 7;
        int orow = rowBase + rr;
        float s  = sStats[rr][0];
        float q  = sStats[rr][1];
        float dv = sStats[rr][2 + n];
        float mu   = s * (1.0f / 1024.0f);
        float var  = fmaf(-mu, mu, q * (1.0f / 1024.0f));
        float rstd = __frcp_rn(__fsqrt_rn(var + 1e-5f));
        float lg   = fmaf(rstd, fmaf(-mu, sSB[n], dv), sSB[8 + n]);
        out[(size_t)orow * NL + n] = tanh4_round(lg);
    }
}

extern "C" void kernel_launch(void* const* d_in, const int* in_sizes, int n_in,
                              void* d_out, int out_size)
{
    const float* x     = (const float*)d_in[0];  // [8,8192,1024]
    const float* gamma = (const float*)d_in[1];  // [1024]
    const float* beta  = (const float*)d_in[2];  // [1024]
    const float* W     = (const float*)d_in[3];  // [8,1024]
    float* out = (float*)d_out;                  // [8,8192,8]

    static int smem_set = 0;
    if (!smem_set) {
        cudaFuncSetAttribute(fsq_kernel,
                             cudaFuncAttributeMaxDynamicSharedMemorySize,
                             SMEM_TOTAL);
        smem_set = 1;
    }

    int rows = in_sizes[0] / D;
    int grid = (rows + ROWS_PB - 1) / ROWS_PB;
    fsq_kernel<<<grid, 256, SMEM_TOTAL>>>(x, gamma, beta, W, out, rows);
}